// round 1
// baseline (speedup 1.0000x reference)
#include <cuda_runtime.h>
#include <math.h>

// Fixed problem shapes
#define C_  2048
#define H_  16
#define DH  128
#define S_  1024
#define T_  256
#define B_  4
#define L_  4096   // B_*S_
#define LY  1024   // B_*T_
#define F_  8192

// ---------------- scratch (device globals; no runtime allocation) ----------
__device__ float g_XM[(size_t)L_ * C_];
__device__ float g_Q [(size_t)L_ * C_];
__device__ float g_K [(size_t)L_ * C_];
__device__ float g_V [(size_t)L_ * C_];
__device__ float g_AT[(size_t)L_ * C_];
__device__ float g_X1[(size_t)L_ * C_];
__device__ float g_X2[(size_t)L_ * C_];
__device__ float g_SC[(size_t)B_ * H_ * S_ * S_];   // 256 MB score scratch
__device__ float g_HB[(size_t)L_ * F_];             // 128 MB MLP hidden

// ---------------- helpers ---------------------------------------------------
__device__ __forceinline__ float gelu_tanh(float x) {
    float x3 = x * x * x;
    return 0.5f * x * (1.0f + tanhf(0.7978845608028654f * (x + 0.044715f * x3)));
}

// Epilogue codes
#define EP_BIAS  0   // out = acc + bias(optional)
#define EP_SCALE 1   // out = acc * alpha
#define EP_GELU  2   // out = gelu(acc + bias)
#define EP_GATED 3   // out = resid + gate*(acc + bias), gate = sstg[n] + tg[m*6C + n]
#define EP_RES   4   // out = resid + (acc + bias)

// ---------------- generic tiled GEMM ----------------------------------------
// Computes, per batch z (b = z/16, h = z%16):
//   C[m,n] = sum_k A[m,k] * B'[k,n]
// where B' = B[n,k] row-major if BT==1 (NT), else B[k,n] row-major (NN).
// All tile dims must divide M,N (128) and K (8) -- true for every call here.
#define BM 128
#define BN 128
#define BK 8

template <int BT>
__global__ __launch_bounds__(256)
void gemm_kernel(const float* __restrict__ A, const float* __restrict__ B,
                 float* __restrict__ Cc,
                 const float* __restrict__ bias,
                 const float* __restrict__ resid,
                 const float* __restrict__ sstg,
                 const float* __restrict__ tg,
                 int M, int N, int K,
                 int lda, int ldb, int ldc,
                 long oAb, long oAh, long oBb, long oBh, long oCb, long oCh,
                 float alpha, int ep)
{
    int z = blockIdx.z;
    int bb = z >> 4;      // batch index   (H_ == 16)
    int hh = z & 15;      // head index
    A  += (long)bb * oAb + (long)hh * oAh;
    B  += (long)bb * oBb + (long)hh * oBh;
    Cc += (long)bb * oCb + (long)hh * oCh;

    __shared__ float As[BK][BM];
    __shared__ float Bs[BK][BN];

    int tid = threadIdx.x;
    int tx = tid & 15;        // 0..15  -> n
    int ty = tid >> 4;        // 0..15  -> m
    int m0 = blockIdx.y * BM;
    int n0 = blockIdx.x * BN;

    float acc[8][8];
#pragma unroll
    for (int i = 0; i < 8; i++)
#pragma unroll
        for (int j = 0; j < 8; j++) acc[i][j] = 0.0f;

    int arow = tid >> 1;            // 0..127
    int acol = (tid & 1) * 4;       // 0 or 4

    for (int k0 = 0; k0 < K; k0 += BK) {
        // load A tile (128 x 8), transposed into As[k][m]
        float4 av = *(const float4*)(A + (long)(m0 + arow) * lda + k0 + acol);
        As[acol + 0][arow] = av.x;
        As[acol + 1][arow] = av.y;
        As[acol + 2][arow] = av.z;
        As[acol + 3][arow] = av.w;

        if (BT) {
            // B is [N,K] row-major -> load like A, transpose to Bs[k][n]
            float4 bv = *(const float4*)(B + (long)(n0 + arow) * ldb + k0 + acol);
            Bs[acol + 0][arow] = bv.x;
            Bs[acol + 1][arow] = bv.y;
            Bs[acol + 2][arow] = bv.z;
            Bs[acol + 3][arow] = bv.w;
        } else {
            // B is [K,N] row-major -> direct coalesced copy
            int brow = tid >> 5;          // 0..7
            int bcol = (tid & 31) * 4;    // 0..124
            float4 bv = *(const float4*)(B + (long)(k0 + brow) * ldb + n0 + bcol);
            *(float4*)&Bs[brow][bcol] = bv;
        }
        __syncthreads();

#pragma unroll
        for (int kk = 0; kk < BK; kk++) {
            float ra[8], rb[8];
#pragma unroll
            for (int i = 0; i < 8; i++) ra[i] = As[kk][ty * 8 + i];
#pragma unroll
            for (int j = 0; j < 8; j++) rb[j] = Bs[kk][tx * 8 + j];
#pragma unroll
            for (int i = 0; i < 8; i++)
#pragma unroll
                for (int j = 0; j < 8; j++) acc[i][j] = fmaf(ra[i], rb[j], acc[i][j]);
        }
        __syncthreads();
    }

    // epilogue
#pragma unroll
    for (int i = 0; i < 8; i++) {
        int gm = m0 + ty * 8 + i;
#pragma unroll
        for (int j = 0; j < 8; j++) {
            int gn = n0 + tx * 8 + j;
            float v = acc[i][j];
            if (ep == EP_SCALE) v *= alpha;
            if (bias) v += bias[gn];
            if (ep == EP_GELU) v = gelu_tanh(v);
            if (ep == EP_GATED) {
                float g = sstg[gn] + tg[(long)gm * (6 * C_) + gn];
                v = resid[(long)gm * ldc + gn] + g * v;
            } else if (ep == EP_RES) {
                v = resid[(long)gm * ldc + gn] + v;
            }
            Cc[(long)gm * ldc + gn] = v;
        }
    }
}

// ---------------- LayerNorm + modulation ------------------------------------
// out[l,:] = ln(x[l,:]) * (1 + (sst[si]+t[l,si])) + (sst[shi]+t[l,shi])
__global__ __launch_bounds__(256)
void ln_mod_kernel(const float* __restrict__ x, float* __restrict__ out,
                   const float* __restrict__ sst, const float* __restrict__ t,
                   int shi, int si)
{
    int l = blockIdx.x;
    const float* xr = x + (long)l * C_;
    const float* tr = t + (long)l * (6 * C_);
    __shared__ float r1[256], r2[256];
    int tid = threadIdx.x;

    float s = 0.f, s2 = 0.f;
    for (int i = tid; i < C_; i += 256) {
        float v = xr[i];
        s += v; s2 += v * v;
    }
    r1[tid] = s; r2[tid] = s2;
    __syncthreads();
    for (int st = 128; st > 0; st >>= 1) {
        if (tid < st) { r1[tid] += r1[tid + st]; r2[tid] += r2[tid + st]; }
        __syncthreads();
    }
    float mean = r1[0] * (1.0f / C_);
    float var  = r2[0] * (1.0f / C_) - mean * mean;
    float rstd = rsqrtf(var + 1e-6f);

    float* orow = out + (long)l * C_;
    for (int i = tid; i < C_; i += 256) {
        float sc = sst[si * C_ + i] + tr[si * C_ + i];
        float sh = sst[shi * C_ + i] + tr[shi * C_ + i];
        orow[i] = (xr[i] - mean) * rstd * (1.0f + sc) + sh;
    }
}

// ---------------- RoPE (in-place on Q and K) ---------------------------------
__global__ void rope_kernel(float* __restrict__ Q, float* __restrict__ Kk,
                            const float* __restrict__ freqs)
{
    int idx = blockIdx.x * blockDim.x + threadIdx.x;   // over L_ * C_/2 pairs
    if (idx >= L_ * (C_ / 2)) return;
    int l = idx / (C_ / 2);
    int r = idx - l * (C_ / 2);
    int h = r >> 6;            // /64
    int i = r & 63;
    int s = l & (S_ - 1);
    float f = freqs[s * 64 + i];
    float c = cosf(f), sn = sinf(f);
    long base = (long)l * C_ + h * DH + 2 * i;
    float a = Q[base], b = Q[base + 1];
    Q[base]     = a * c - b * sn;
    Q[base + 1] = a * sn + b * c;
    a = Kk[base]; b = Kk[base + 1];
    Kk[base]     = a * c - b * sn;
    Kk[base + 1] = a * sn + b * c;
}

// ---------------- row softmax ------------------------------------------------
__global__ __launch_bounds__(256)
void softmax_kernel(float* __restrict__ sc, int n)
{
    long row = blockIdx.x;
    float* p = sc + row * (long)n;
    int tid = threadIdx.x;
    __shared__ float red[256];

    float m = -1e30f;
    for (int i = tid; i < n; i += 256) m = fmaxf(m, p[i]);
    red[tid] = m; __syncthreads();
    for (int s = 128; s > 0; s >>= 1) {
        if (tid < s) red[tid] = fmaxf(red[tid], red[tid + s]);
        __syncthreads();
    }
    m = red[0];
    __syncthreads();

    float sum = 0.f;
    for (int i = tid; i < n; i += 256) {
        float e = expf(p[i] - m);
        p[i] = e;
        sum += e;
    }
    red[tid] = sum; __syncthreads();
    for (int s = 128; s > 0; s >>= 1) {
        if (tid < s) red[tid] += red[tid + s];
        __syncthreads();
    }
    float inv = 1.0f / red[0];
    for (int i = tid; i < n; i += 256) p[i] *= inv;
}

// ---------------- host-side launch helpers ----------------------------------
static void launch_gemm(const float* A, const float* B, float* Cc,
                        const float* bias, const float* resid,
                        const float* sstg, const float* tg,
                        int M, int N, int K,
                        int lda, int ldb, int ldc,
                        long oAb, long oAh, long oBb, long oBh, long oCb, long oCh,
                        int Z, float alpha, int ep, bool bt)
{
    dim3 grid(N / BN, M / BM, Z), blk(256);
    if (bt)
        gemm_kernel<1><<<grid, blk>>>(A, B, Cc, bias, resid, sstg, tg,
                                      M, N, K, lda, ldb, ldc,
                                      oAb, oAh, oBb, oBh, oCb, oCh, alpha, ep);
    else
        gemm_kernel<0><<<grid, blk>>>(A, B, Cc, bias, resid, sstg, tg,
                                      M, N, K, lda, ldb, ldc,
                                      oAb, oAh, oBb, oBh, oCb, oCh, alpha, ep);
}

extern "C" void kernel_launch(void* const* d_in, const int* in_sizes, int n_in,
                              void* d_out, int out_size)
{
    (void)in_sizes; (void)n_in; (void)out_size;
    const float* x     = (const float*)d_in[0];
    const float* y     = (const float*)d_in[1];
    const float* t     = (const float*)d_in[2];
    const float* freqs = (const float*)d_in[3];
    const float* sst   = (const float*)d_in[4];
    const float* Wq_s  = (const float*)d_in[5];
    const float* bq_s  = (const float*)d_in[6];
    const float* Wk_s  = (const float*)d_in[7];
    const float* bk_s  = (const float*)d_in[8];
    const float* Wv_s  = (const float*)d_in[9];
    const float* bv_s  = (const float*)d_in[10];
    const float* Wo_s  = (const float*)d_in[11];
    const float* bo_s  = (const float*)d_in[12];
    const float* Wq_c  = (const float*)d_in[13];
    const float* bq_c  = (const float*)d_in[14];
    const float* Wk_c  = (const float*)d_in[15];
    const float* bk_c  = (const float*)d_in[16];
    const float* Wv_c  = (const float*)d_in[17];
    const float* bv_c  = (const float*)d_in[18];
    const float* Wo_c  = (const float*)d_in[19];
    const float* bo_c  = (const float*)d_in[20];
    const float* W_fc1 = (const float*)d_in[21];
    const float* b_fc1 = (const float*)d_in[22];
    const float* W_fc2 = (const float*)d_in[23];
    const float* b_fc2 = (const float*)d_in[24];
    float* out = (float*)d_out;

    void *pXM, *pQ, *pK, *pV, *pAT, *pX1, *pX2, *pSC, *pHB;
    cudaGetSymbolAddress(&pXM, g_XM);
    cudaGetSymbolAddress(&pQ,  g_Q);
    cudaGetSymbolAddress(&pK,  g_K);
    cudaGetSymbolAddress(&pV,  g_V);
    cudaGetSymbolAddress(&pAT, g_AT);
    cudaGetSymbolAddress(&pX1, g_X1);
    cudaGetSymbolAddress(&pX2, g_X2);
    cudaGetSymbolAddress(&pSC, g_SC);
    cudaGetSymbolAddress(&pHB, g_HB);
    float* XM = (float*)pXM;  float* Q  = (float*)pQ;
    float* K  = (float*)pK;   float* V  = (float*)pV;
    float* AT = (float*)pAT;  float* X1 = (float*)pX1;
    float* X2 = (float*)pX2;  float* SC = (float*)pSC;
    float* HB = (float*)pHB;

    const float att_scale = 0.08838834764831845f;  // 1/sqrt(128)

    // 1. LN + MSA modulation: XM = ln(x)*(1+scale_msa)+shift_msa
    ln_mod_kernel<<<L_, 256>>>(x, XM, sst, t, /*shift*/0, /*scale*/1);

    // 2-4. self-attn projections (NT GEMMs)
    launch_gemm(XM, Wq_s, Q, bq_s, 0, 0, 0, L_, C_, C_, C_, C_, C_,
                0,0,0,0,0,0, 1, 1.f, EP_BIAS, true);
    launch_gemm(XM, Wk_s, K, bk_s, 0, 0, 0, L_, C_, C_, C_, C_, C_,
                0,0,0,0,0,0, 1, 1.f, EP_BIAS, true);
    launch_gemm(XM, Wv_s, V, bv_s, 0, 0, 0, L_, C_, C_, C_, C_, C_,
                0,0,0,0,0,0, 1, 1.f, EP_BIAS, true);

    // 5. RoPE on Q,K
    {
        int total = L_ * (C_ / 2);
        rope_kernel<<<(total + 255) / 256, 256>>>(Q, K, freqs);
    }

    // 6. scores = (Q . K^T) * scale, batched over 64 (b,h)
    launch_gemm(Q, K, SC, 0, 0, 0, 0,
                S_, S_, DH, C_, C_, S_,
                (long)S_ * C_, DH, (long)S_ * C_, DH,
                (long)H_ * S_ * S_, (long)S_ * S_,
                B_ * H_, att_scale, EP_SCALE, true);

    // 7. softmax rows (B*H*S rows of length S)
    softmax_kernel<<<B_ * H_ * S_, 256>>>(SC, S_);

    // 8. AT = P . V  (NN, batched), written to (L,C) layout
    launch_gemm(SC, V, AT, 0, 0, 0, 0,
                S_, DH, S_, S_, C_, C_,
                (long)H_ * S_ * S_, (long)S_ * S_, (long)S_ * C_, DH,
                (long)S_ * C_, DH,
                B_ * H_, 1.f, EP_BIAS, false);

    // 9. X1 = x + gate_msa * (AT . Wo_s^T + bo_s)
    launch_gemm(AT, Wo_s, X1, bo_s, x, sst + 2 * C_, t + 2 * C_,
                L_, C_, C_, C_, C_, C_,
                0,0,0,0,0,0, 1, 1.f, EP_GATED, true);

    // 10-12. cross-attn projections
    launch_gemm(X1, Wq_c, Q, bq_c, 0, 0, 0, L_, C_, C_, C_, C_, C_,
                0,0,0,0,0,0, 1, 1.f, EP_BIAS, true);
    launch_gemm(y, Wk_c, K, bk_c, 0, 0, 0, LY, C_, C_, C_, C_, C_,
                0,0,0,0,0,0, 1, 1.f, EP_BIAS, true);
    launch_gemm(y, Wv_c, V, bv_c, 0, 0, 0, LY, C_, C_, C_, C_, C_,
                0,0,0,0,0,0, 1, 1.f, EP_BIAS, true);

    // 13. cross scores (S x T per head)
    launch_gemm(Q, K, SC, 0, 0, 0, 0,
                S_, T_, DH, C_, C_, T_,
                (long)S_ * C_, DH, (long)T_ * C_, DH,
                (long)H_ * S_ * T_, (long)S_ * T_,
                B_ * H_, att_scale, EP_SCALE, true);

    // 14. softmax rows of length T
    softmax_kernel<<<B_ * H_ * S_, 256>>>(SC, T_);

    // 15. AT = P . V (cross)
    launch_gemm(SC, V, AT, 0, 0, 0, 0,
                S_, DH, T_, T_, C_, C_,
                (long)H_ * S_ * T_, (long)S_ * T_, (long)T_ * C_, DH,
                (long)S_ * C_, DH,
                B_ * H_, 1.f, EP_BIAS, false);

    // 16. X2 = X1 + (AT . Wo_c^T + bo_c)
    launch_gemm(AT, Wo_c, X2, bo_c, X1, 0, 0,
                L_, C_, C_, C_, C_, C_,
                0,0,0,0,0,0, 1, 1.f, EP_RES, true);

    // 17. LN + MLP modulation
    ln_mod_kernel<<<L_, 256>>>(X2, XM, sst, t, /*shift*/3, /*scale*/4);

    // 18. HB = gelu(XM . W_fc1^T + b_fc1)
    launch_gemm(XM, W_fc1, HB, b_fc1, 0, 0, 0,
                L_, F_, C_, C_, C_, F_,
                0,0,0,0,0,0, 1, 1.f, EP_GELU, true);

    // 19. out = X2 + gate_mlp * (HB . W_fc2^T + b_fc2)
    launch_gemm(HB, W_fc2, out, b_fc2, X2, sst + 5 * C_, t + 5 * C_,
                L_, C_, F_, F_, F_, C_,
                0,0,0,0,0,0, 1, 1.f, EP_GATED, true);
}

// round 3
// speedup vs baseline: 2.0244x; 2.0244x over previous
#include <cuda_runtime.h>
#include <cuda_bf16.h>
#include <cstdint>
#include <math.h>

// Fixed problem shapes
#define C_  2048
#define H_  16
#define DH  128
#define S_  1024
#define T_  256
#define B_  4
#define L_  4096   // B_*S_
#define LY  1024   // B_*T_
#define F_  8192

// ---------------- scratch (device globals; no runtime allocation) ----------
__device__ float g_XM[(size_t)L_ * C_];
__device__ float g_Q [(size_t)L_ * C_];
__device__ float g_K [(size_t)L_ * C_];
__device__ float g_V [(size_t)L_ * C_];
__device__ float g_AT[(size_t)L_ * C_];
__device__ float g_X1[(size_t)L_ * C_];
__device__ float g_X2[(size_t)L_ * C_];
__device__ float g_SC[(size_t)B_ * H_ * S_ * S_];   // 256 MB score scratch
__device__ float g_HB[(size_t)L_ * F_];             // 128 MB MLP hidden

// bf16 split operand scratch
__device__ __nv_bfloat16 g_Ahi[(size_t)L_ * F_];
__device__ __nv_bfloat16 g_Alo[(size_t)L_ * F_];
__device__ __nv_bfloat16 g_Whi[(size_t)F_ * C_];
__device__ __nv_bfloat16 g_Wlo[(size_t)F_ * C_];

// ---------------- helpers ---------------------------------------------------
__device__ __forceinline__ float gelu_tanh(float x) {
    float x3 = x * x * x;
    return 0.5f * x * (1.0f + tanhf(0.7978845608028654f * (x + 0.044715f * x3)));
}

#define EP_BIAS  0
#define EP_SCALE 1
#define EP_GELU  2
#define EP_GATED 3
#define EP_RES   4

__device__ __forceinline__ uint32_t smem_u32(const void* p) {
    uint32_t a;
    asm("{ .reg .u64 t; cvta.to.shared.u64 t, %1; cvt.u32.u64 %0, t; }"
        : "=r"(a) : "l"(p));
    return a;
}

__device__ __forceinline__ void cp16(uint32_t dst, const void* src) {
    asm volatile("cp.async.cg.shared.global [%0], [%1], 16;\n"
                 :: "r"(dst), "l"(src));
}
#define CP_COMMIT() asm volatile("cp.async.commit_group;" ::: "memory")
template <int N>
__device__ __forceinline__ void cp_wait() {
    asm volatile("cp.async.wait_group %0;" :: "n"(N) : "memory");
}

__device__ __forceinline__ void ldsm_x4(uint32_t* r, uint32_t addr) {
    asm volatile("ldmatrix.sync.aligned.m8n8.x4.shared.b16 {%0,%1,%2,%3}, [%4];"
                 : "=r"(r[0]), "=r"(r[1]), "=r"(r[2]), "=r"(r[3]) : "r"(addr));
}

__device__ __forceinline__ void mma16816(float* c, const uint32_t* a,
                                         const uint32_t* b) {
    asm volatile(
        "mma.sync.aligned.m16n8k16.row.col.f32.bf16.bf16.f32 "
        "{%0,%1,%2,%3}, {%4,%5,%6,%7}, {%8,%9}, {%0,%1,%2,%3};"
        : "+f"(c[0]), "+f"(c[1]), "+f"(c[2]), "+f"(c[3])
        : "r"(a[0]), "r"(a[1]), "r"(a[2]), "r"(a[3]), "r"(b[0]), "r"(b[1]));
}

// ================= split-bf16 mma.sync GEMM =================================
// C[M,N] = (Ahi+Alo)[M,K] . (Bhi+Blo)[N,K]^T   (drops lo*lo term, ~2^-18)
// Block tile 128x128, K-chunk 32, 3-stage cp.async pipeline.
// 8 warps = 2(M) x 4(N); warp tile 64x32.
#define TCBM 128
#define TCBN 128
#define TCBK 32
#define STAGES 3
#define ROWB 80                         // padded row stride in bytes (32 bf16 + 8 pad)
#define ARR_BYTES (128 * ROWB)          // 10240 per array
#define OFF_AHI 0
#define OFF_ALO (1 * ARR_BYTES)
#define OFF_BHI (2 * ARR_BYTES)
#define OFF_BLO (3 * ARR_BYTES)
#define STG_BYTES (4 * ARR_BYTES)       // 40960
#define DSMEM_BYTES (STAGES * STG_BYTES)

__device__ __forceinline__ void load_chunk(
    uint32_t st, const __nv_bfloat16* __restrict__ Ahi,
    const __nv_bfloat16* __restrict__ Alo,
    const __nv_bfloat16* __restrict__ Bhi,
    const __nv_bfloat16* __restrict__ Blo,
    int m0, int n0, int k0, int lda, int ldb, int tid)
{
    int r  = tid >> 1;             // 0..127
    int ch = (tid & 1) * 2;        // 0 or 2 (two 16B chunks each)
    uint32_t doff = (uint32_t)(r * ROWB + ch * 16);
    long ga = (long)(m0 + r) * lda + k0 + ch * 8;
    long gb = (long)(n0 + r) * ldb + k0 + ch * 8;
    cp16(st + OFF_AHI + doff,      Ahi + ga);
    cp16(st + OFF_AHI + doff + 16, Ahi + ga + 8);
    cp16(st + OFF_ALO + doff,      Alo + ga);
    cp16(st + OFF_ALO + doff + 16, Alo + ga + 8);
    cp16(st + OFF_BHI + doff,      Bhi + gb);
    cp16(st + OFF_BHI + doff + 16, Bhi + gb + 8);
    cp16(st + OFF_BLO + doff,      Blo + gb);
    cp16(st + OFF_BLO + doff + 16, Blo + gb + 8);
}

__global__ __launch_bounds__(256, 1)
void tc_gemm(const __nv_bfloat16* __restrict__ Ahi, const __nv_bfloat16* __restrict__ Alo,
             const __nv_bfloat16* __restrict__ Bhi, const __nv_bfloat16* __restrict__ Blo,
             float* __restrict__ Cc,
             const float* __restrict__ bias, const float* __restrict__ resid,
             const float* __restrict__ sstg, const float* __restrict__ tg,
             int M, int N, int K, int ldc, int ep)
{
    extern __shared__ char dsm[];
    uint32_t sbase = smem_u32(dsm);

    int tid  = threadIdx.x;
    int wid  = tid >> 5;
    int lane = tid & 31;
    int warp_m = wid >> 2;         // 0..1
    int warp_n = wid & 3;          // 0..3
    int m0 = blockIdx.y * TCBM;
    int n0 = blockIdx.x * TCBN;
    int lda = K, ldb = K;
    int NC = K >> 5;               // K / 32

    float acc[4][4][4];
#pragma unroll
    for (int i = 0; i < 4; i++)
#pragma unroll
        for (int j = 0; j < 4; j++)
#pragma unroll
            for (int q = 0; q < 4; q++) acc[i][j][q] = 0.f;

    // prologue: chunks 0 and 1
    load_chunk(sbase, Ahi, Alo, Bhi, Blo, m0, n0, 0, lda, ldb, tid);
    CP_COMMIT();
    load_chunk(sbase + STG_BYTES, Ahi, Alo, Bhi, Blo, m0, n0, TCBK, lda, ldb, tid);
    CP_COMMIT();

    // per-warp ldmatrix base offsets (within a stage)
    uint32_t aoff = (uint32_t)((warp_m * 64 + (lane & 15)) * ROWB + (lane >> 4) * 16);
    int brow = warp_n * 32 + (lane & 7) + ((lane >> 4) & 1) * 8;
    uint32_t boff = (uint32_t)(brow * ROWB + ((lane >> 3) & 1) * 16);

    for (int c = 0; c < NC; c++) {
        if (c + 2 < NC)
            load_chunk(sbase + (uint32_t)((c + 2) % STAGES) * STG_BYTES,
                       Ahi, Alo, Bhi, Blo, m0, n0, (c + 2) * TCBK, lda, ldb, tid);
        CP_COMMIT();
        cp_wait<2>();
        __syncthreads();

        uint32_t st = sbase + (uint32_t)(c % STAGES) * STG_BYTES;
        uint32_t aHi = st + OFF_AHI + aoff;
        uint32_t aLo = st + OFF_ALO + aoff;
        uint32_t bHi = st + OFF_BHI + boff;
        uint32_t bLo = st + OFF_BLO + boff;

#pragma unroll
        for (int ks = 0; ks < 2; ks++) {
            uint32_t ah[4][4], al[4][4], bh[2][4], bl[2][4];
#pragma unroll
            for (int mi = 0; mi < 4; mi++) {
                ldsm_x4(ah[mi], aHi + mi * (16 * ROWB) + ks * 32);
                ldsm_x4(al[mi], aLo + mi * (16 * ROWB) + ks * 32);
            }
#pragma unroll
            for (int nb = 0; nb < 2; nb++) {
                ldsm_x4(bh[nb], bHi + nb * (16 * ROWB) + ks * 32);
                ldsm_x4(bl[nb], bLo + nb * (16 * ROWB) + ks * 32);
            }
#pragma unroll
            for (int mi = 0; mi < 4; mi++)
#pragma unroll
                for (int ni = 0; ni < 4; ni++) {
                    const uint32_t* bhf = &bh[ni >> 1][(ni & 1) * 2];
                    const uint32_t* blf = &bl[ni >> 1][(ni & 1) * 2];
                    mma16816(acc[mi][ni], ah[mi], bhf);
                    mma16816(acc[mi][ni], al[mi], bhf);
                    mma16816(acc[mi][ni], ah[mi], blf);
                }
        }
        __syncthreads();
    }

    // ---------------- epilogue ----------------
    int g = lane >> 2, tq = lane & 3;
#pragma unroll
    for (int mi = 0; mi < 4; mi++) {
        int gmA = m0 + warp_m * 64 + mi * 16 + g;
#pragma unroll
        for (int half = 0; half < 2; half++) {
            int gm = gmA + half * 8;
            const float* tgrow = (ep == EP_GATED) ? (tg + (long)gm * (6 * C_)) : 0;
            const float* rrow  = (ep == EP_GATED || ep == EP_RES)
                                 ? (resid + (long)gm * ldc) : 0;
            float* crow = Cc + (long)gm * ldc;
#pragma unroll
            for (int ni = 0; ni < 4; ni++) {
                int gn = n0 + warp_n * 32 + ni * 8 + 2 * tq;
                float v0 = acc[mi][ni][half * 2];
                float v1 = acc[mi][ni][half * 2 + 1];
                if (bias) {
                    float2 bb = *(const float2*)(bias + gn);
                    v0 += bb.x; v1 += bb.y;
                }
                if (ep == EP_GELU) {
                    v0 = gelu_tanh(v0); v1 = gelu_tanh(v1);
                } else if (ep == EP_GATED) {
                    float2 sg = *(const float2*)(sstg + gn);
                    float2 tg2 = *(const float2*)(tgrow + gn);
                    float2 rr = *(const float2*)(rrow + gn);
                    v0 = rr.x + (sg.x + tg2.x) * v0;
                    v1 = rr.y + (sg.y + tg2.y) * v1;
                } else if (ep == EP_RES) {
                    float2 rr = *(const float2*)(rrow + gn);
                    v0 += rr.x; v1 += rr.y;
                }
                float2 o; o.x = v0; o.y = v1;
                *(float2*)(crow + gn) = o;
            }
        }
    }
}

// ---------------- fp32 split conversion kernel -------------------------------
__global__ __launch_bounds__(256)
void split_kernel(const float* __restrict__ src,
                  __nv_bfloat16* __restrict__ hi, __nv_bfloat16* __restrict__ lo,
                  long n4)
{
    long i = (long)blockIdx.x * 256 + threadIdx.x;
    long stride = (long)gridDim.x * 256;
    for (; i < n4; i += stride) {
        float4 v = ((const float4*)src)[i];
        __nv_bfloat16 h0 = __float2bfloat16(v.x);
        __nv_bfloat16 h1 = __float2bfloat16(v.y);
        __nv_bfloat16 h2 = __float2bfloat16(v.z);
        __nv_bfloat16 h3 = __float2bfloat16(v.w);
        __nv_bfloat16 l0 = __float2bfloat16(v.x - __bfloat162float(h0));
        __nv_bfloat16 l1 = __float2bfloat16(v.y - __bfloat162float(h1));
        __nv_bfloat16 l2 = __float2bfloat16(v.z - __bfloat162float(h2));
        __nv_bfloat16 l3 = __float2bfloat16(v.w - __bfloat162float(h3));
        __nv_bfloat162* hp = (__nv_bfloat162*)hi;
        __nv_bfloat162* lp = (__nv_bfloat162*)lo;
        hp[2 * i]     = __nv_bfloat162(h0, h1);
        hp[2 * i + 1] = __nv_bfloat162(h2, h3);
        lp[2 * i]     = __nv_bfloat162(l0, l1);
        lp[2 * i + 1] = __nv_bfloat162(l2, l3);
    }
}

// ================= fp32 fallback GEMM (attention only) ======================
#define BM 128
#define BN 128
#define BK 8

template <int BT>
__global__ __launch_bounds__(256)
void gemm_kernel(const float* __restrict__ A, const float* __restrict__ B,
                 float* __restrict__ Cc,
                 const float* __restrict__ bias,
                 int M, int N, int K,
                 int lda, int ldb, int ldc,
                 long oAb, long oAh, long oBb, long oBh, long oCb, long oCh,
                 float alpha, int ep)
{
    int z = blockIdx.z;
    int bb = z >> 4;
    int hh = z & 15;
    A  += (long)bb * oAb + (long)hh * oAh;
    B  += (long)bb * oBb + (long)hh * oBh;
    Cc += (long)bb * oCb + (long)hh * oCh;

    __shared__ float As[BK][BM];
    __shared__ float Bs[BK][BN];

    int tid = threadIdx.x;
    int tx = tid & 15;
    int ty = tid >> 4;
    int m0 = blockIdx.y * BM;
    int n0 = blockIdx.x * BN;

    float acc[8][8];
#pragma unroll
    for (int i = 0; i < 8; i++)
#pragma unroll
        for (int j = 0; j < 8; j++) acc[i][j] = 0.0f;

    int arow = tid >> 1;
    int acol = (tid & 1) * 4;

    for (int k0 = 0; k0 < K; k0 += BK) {
        float4 av = *(const float4*)(A + (long)(m0 + arow) * lda + k0 + acol);
        As[acol + 0][arow] = av.x;
        As[acol + 1][arow] = av.y;
        As[acol + 2][arow] = av.z;
        As[acol + 3][arow] = av.w;

        if (BT) {
            float4 bv = *(const float4*)(B + (long)(n0 + arow) * ldb + k0 + acol);
            Bs[acol + 0][arow] = bv.x;
            Bs[acol + 1][arow] = bv.y;
            Bs[acol + 2][arow] = bv.z;
            Bs[acol + 3][arow] = bv.w;
        } else {
            int brow = tid >> 5;
            int bcol = (tid & 31) * 4;
            float4 bv = *(const float4*)(B + (long)(k0 + brow) * ldb + n0 + bcol);
            *(float4*)&Bs[brow][bcol] = bv;
        }
        __syncthreads();

#pragma unroll
        for (int kk = 0; kk < BK; kk++) {
            float ra[8], rb[8];
#pragma unroll
            for (int i = 0; i < 8; i++) ra[i] = As[kk][ty * 8 + i];
#pragma unroll
            for (int j = 0; j < 8; j++) rb[j] = Bs[kk][tx * 8 + j];
#pragma unroll
            for (int i = 0; i < 8; i++)
#pragma unroll
                for (int j = 0; j < 8; j++) acc[i][j] = fmaf(ra[i], rb[j], acc[i][j]);
        }
        __syncthreads();
    }

#pragma unroll
    for (int i = 0; i < 8; i++) {
        int gm = m0 + ty * 8 + i;
#pragma unroll
        for (int j = 0; j < 8; j++) {
            int gn = n0 + tx * 8 + j;
            float v = acc[i][j];
            if (ep == EP_SCALE) v *= alpha;
            if (bias) v += bias[gn];
            Cc[(long)gm * ldc + gn] = v;
        }
    }
}

// ---------------- LayerNorm + modulation ------------------------------------
__global__ __launch_bounds__(256)
void ln_mod_kernel(const float* __restrict__ x, float* __restrict__ out,
                   const float* __restrict__ sst, const float* __restrict__ t,
                   int shi, int si)
{
    int l = blockIdx.x;
    const float* xr = x + (long)l * C_;
    const float* tr = t + (long)l * (6 * C_);
    __shared__ float r1[256], r2[256];
    int tid = threadIdx.x;

    float s = 0.f, s2 = 0.f;
    for (int i = tid; i < C_; i += 256) {
        float v = xr[i];
        s += v; s2 += v * v;
    }
    r1[tid] = s; r2[tid] = s2;
    __syncthreads();
    for (int st = 128; st > 0; st >>= 1) {
        if (tid < st) { r1[tid] += r1[tid + st]; r2[tid] += r2[tid + st]; }
        __syncthreads();
    }
    float mean = r1[0] * (1.0f / C_);
    float var  = r2[0] * (1.0f / C_) - mean * mean;
    float rstd = rsqrtf(var + 1e-6f);

    float* orow = out + (long)l * C_;
    for (int i = tid; i < C_; i += 256) {
        float sc = sst[si * C_ + i] + tr[si * C_ + i];
        float sh = sst[shi * C_ + i] + tr[shi * C_ + i];
        orow[i] = (xr[i] - mean) * rstd * (1.0f + sc) + sh;
    }
}

// ---------------- RoPE (in-place on Q and K) ---------------------------------
__global__ void rope_kernel(float* __restrict__ Q, float* __restrict__ Kk,
                            const float* __restrict__ freqs)
{
    int idx = blockIdx.x * blockDim.x + threadIdx.x;
    if (idx >= L_ * (C_ / 2)) return;
    int l = idx / (C_ / 2);
    int r = idx - l * (C_ / 2);
    int h = r >> 6;
    int i = r & 63;
    int s = l & (S_ - 1);
    float f = freqs[s * 64 + i];
    float c = cosf(f), sn = sinf(f);
    long base = (long)l * C_ + h * DH + 2 * i;
    float a = Q[base], b = Q[base + 1];
    Q[base]     = a * c - b * sn;
    Q[base + 1] = a * sn + b * c;
    a = Kk[base]; b = Kk[base + 1];
    Kk[base]     = a * c - b * sn;
    Kk[base + 1] = a * sn + b * c;
}

// ---------------- row softmax ------------------------------------------------
__global__ __launch_bounds__(256)
void softmax_kernel(float* __restrict__ sc, int n)
{
    long row = blockIdx.x;
    float* p = sc + row * (long)n;
    int tid = threadIdx.x;
    __shared__ float red[256];

    float m = -1e30f;
    for (int i = tid; i < n; i += 256) m = fmaxf(m, p[i]);
    red[tid] = m; __syncthreads();
    for (int s = 128; s > 0; s >>= 1) {
        if (tid < s) red[tid] = fmaxf(red[tid], red[tid + s]);
        __syncthreads();
    }
    m = red[0];
    __syncthreads();

    float sum = 0.f;
    for (int i = tid; i < n; i += 256) {
        float e = expf(p[i] - m);
        p[i] = e;
        sum += e;
    }
    red[tid] = sum; __syncthreads();
    for (int s = 128; s > 0; s >>= 1) {
        if (tid < s) red[tid] += red[tid + s];
        __syncthreads();
    }
    float inv = 1.0f / red[0];
    for (int i = tid; i < n; i += 256) p[i] *= inv;
}

// ---------------- host-side launch helpers ----------------------------------
static void launch_gemm_f32(const float* A, const float* B, float* Cc,
                            const float* bias,
                            int M, int N, int K,
                            int lda, int ldb, int ldc,
                            long oAb, long oAh, long oBb, long oBh,
                            long oCb, long oCh,
                            int Z, float alpha, int ep, bool bt)
{
    dim3 grid(N / BN, M / BM, Z), blk(256);
    if (bt)
        gemm_kernel<1><<<grid, blk>>>(A, B, Cc, bias, M, N, K, lda, ldb, ldc,
                                      oAb, oAh, oBb, oBh, oCb, oCh, alpha, ep);
    else
        gemm_kernel<0><<<grid, blk>>>(A, B, Cc, bias, M, N, K, lda, ldb, ldc,
                                      oAb, oAh, oBb, oBh, oCb, oCh, alpha, ep);
}

static void launch_tc_gemm(const __nv_bfloat16* Ahi, const __nv_bfloat16* Alo,
                           const __nv_bfloat16* Whi, const __nv_bfloat16* Wlo,
                           float* Cc, const float* bias, const float* resid,
                           const float* sstg, const float* tg,
                           int M, int N, int K, int ldc, int ep)
{
    dim3 grid(N / TCBN, M / TCBM), blk(256);
    tc_gemm<<<grid, blk, DSMEM_BYTES>>>(Ahi, Alo, Whi, Wlo, Cc,
                                        bias, resid, sstg, tg,
                                        M, N, K, ldc, ep);
}

static void launch_split(const float* src, __nv_bfloat16* hi, __nv_bfloat16* lo,
                         long nelem)
{
    long n4 = nelem / 4;
    int blocks = 2048;
    split_kernel<<<blocks, 256>>>(src, hi, lo, n4);
}

extern "C" void kernel_launch(void* const* d_in, const int* in_sizes, int n_in,
                              void* d_out, int out_size)
{
    (void)in_sizes; (void)n_in; (void)out_size;
    const float* x     = (const float*)d_in[0];
    const float* y     = (const float*)d_in[1];
    const float* t     = (const float*)d_in[2];
    const float* freqs = (const float*)d_in[3];
    const float* sst   = (const float*)d_in[4];
    const float* Wq_s  = (const float*)d_in[5];
    const float* bq_s  = (const float*)d_in[6];
    const float* Wk_s  = (const float*)d_in[7];
    const float* bk_s  = (const float*)d_in[8];
    const float* Wv_s  = (const float*)d_in[9];
    const float* bv_s  = (const float*)d_in[10];
    const float* Wo_s  = (const float*)d_in[11];
    const float* bo_s  = (const float*)d_in[12];
    const float* Wq_c  = (const float*)d_in[13];
    const float* bq_c  = (const float*)d_in[14];
    const float* Wk_c  = (const float*)d_in[15];
    const float* bk_c  = (const float*)d_in[16];
    const float* Wv_c  = (const float*)d_in[17];
    const float* bv_c  = (const float*)d_in[18];
    const float* Wo_c  = (const float*)d_in[19];
    const float* bo_c  = (const float*)d_in[20];
    const float* W_fc1 = (const float*)d_in[21];
    const float* b_fc1 = (const float*)d_in[22];
    const float* W_fc2 = (const float*)d_in[23];
    const float* b_fc2 = (const float*)d_in[24];
    float* out = (float*)d_out;

    cudaFuncSetAttribute(tc_gemm, cudaFuncAttributeMaxDynamicSharedMemorySize,
                         DSMEM_BYTES);

    void *pXM, *pQ, *pK, *pV, *pAT, *pX1, *pX2, *pSC, *pHB;
    void *pAhi, *pAlo, *pWhi, *pWlo;
    cudaGetSymbolAddress(&pXM, g_XM);
    cudaGetSymbolAddress(&pQ,  g_Q);
    cudaGetSymbolAddress(&pK,  g_K);
    cudaGetSymbolAddress(&pV,  g_V);
    cudaGetSymbolAddress(&pAT, g_AT);
    cudaGetSymbolAddress(&pX1, g_X1);
    cudaGetSymbolAddress(&pX2, g_X2);
    cudaGetSymbolAddress(&pSC, g_SC);
    cudaGetSymbolAddress(&pHB, g_HB);
    cudaGetSymbolAddress(&pAhi, g_Ahi);
    cudaGetSymbolAddress(&pAlo, g_Alo);
    cudaGetSymbolAddress(&pWhi, g_Whi);
    cudaGetSymbolAddress(&pWlo, g_Wlo);
    float* XM = (float*)pXM;  float* Q  = (float*)pQ;
    float* K  = (float*)pK;   float* V  = (float*)pV;
    float* AT = (float*)pAT;  float* X1 = (float*)pX1;
    float* X2 = (float*)pX2;  float* SC = (float*)pSC;
    float* HB = (float*)pHB;
    __nv_bfloat16* Ahi = (__nv_bfloat16*)pAhi;
    __nv_bfloat16* Alo = (__nv_bfloat16*)pAlo;
    __nv_bfloat16* Whi = (__nv_bfloat16*)pWhi;
    __nv_bfloat16* Wlo = (__nv_bfloat16*)pWlo;

    const float att_scale = 0.08838834764831845f;  // 1/sqrt(128)

    // 1. LN + MSA modulation
    ln_mod_kernel<<<L_, 256>>>(x, XM, sst, t, 0, 1);

    // 2-4. self-attn projections on mma.sync
    launch_split(XM, Ahi, Alo, (long)L_ * C_);
    launch_split(Wq_s, Whi, Wlo, (long)C_ * C_);
    launch_tc_gemm(Ahi, Alo, Whi, Wlo, Q, bq_s, 0, 0, 0, L_, C_, C_, C_, EP_BIAS);
    launch_split(Wk_s, Whi, Wlo, (long)C_ * C_);
    launch_tc_gemm(Ahi, Alo, Whi, Wlo, K, bk_s, 0, 0, 0, L_, C_, C_, C_, EP_BIAS);
    launch_split(Wv_s, Whi, Wlo, (long)C_ * C_);
    launch_tc_gemm(Ahi, Alo, Whi, Wlo, V, bv_s, 0, 0, 0, L_, C_, C_, C_, EP_BIAS);

    // 5. RoPE on Q,K
    {
        int total = L_ * (C_ / 2);
        rope_kernel<<<(total + 255) / 256, 256>>>(Q, K, freqs);
    }

    // 6. scores = (Q . K^T) * scale (fp32, batched over 64)
    launch_gemm_f32(Q, K, SC, 0,
                    S_, S_, DH, C_, C_, S_,
                    (long)S_ * C_, DH, (long)S_ * C_, DH,
                    (long)H_ * S_ * S_, (long)S_ * S_,
                    B_ * H_, att_scale, EP_SCALE, true);

    // 7. softmax
    softmax_kernel<<<B_ * H_ * S_, 256>>>(SC, S_);

    // 8. AT = P . V
    launch_gemm_f32(SC, V, AT, 0,
                    S_, DH, S_, S_, C_, C_,
                    (long)H_ * S_ * S_, (long)S_ * S_, (long)S_ * C_, DH,
                    (long)S_ * C_, DH,
                    B_ * H_, 1.f, EP_BIAS, false);

    // 9. X1 = x + gate_msa * (AT . Wo_s^T + bo_s)
    launch_split(AT, Ahi, Alo, (long)L_ * C_);
    launch_split(Wo_s, Whi, Wlo, (long)C_ * C_);
    launch_tc_gemm(Ahi, Alo, Whi, Wlo, X1, bo_s, x, sst + 2 * C_, t + 2 * C_,
                   L_, C_, C_, C_, EP_GATED);

    // 10-12. cross-attn projections
    launch_split(X1, Ahi, Alo, (long)L_ * C_);
    launch_split(Wq_c, Whi, Wlo, (long)C_ * C_);
    launch_tc_gemm(Ahi, Alo, Whi, Wlo, Q, bq_c, 0, 0, 0, L_, C_, C_, C_, EP_BIAS);
    launch_split(y, Ahi, Alo, (long)LY * C_);
    launch_split(Wk_c, Whi, Wlo, (long)C_ * C_);
    launch_tc_gemm(Ahi, Alo, Whi, Wlo, K, bk_c, 0, 0, 0, LY, C_, C_, C_, EP_BIAS);
    launch_split(Wv_c, Whi, Wlo, (long)C_ * C_);
    launch_tc_gemm(Ahi, Alo, Whi, Wlo, V, bv_c, 0, 0, 0, LY, C_, C_, C_, EP_BIAS);

    // 13. cross scores
    launch_gemm_f32(Q, K, SC, 0,
                    S_, T_, DH, C_, C_, T_,
                    (long)S_ * C_, DH, (long)T_ * C_, DH,
                    (long)H_ * S_ * T_, (long)S_ * T_,
                    B_ * H_, att_scale, EP_SCALE, true);

    // 14. softmax (rows of length T)
    softmax_kernel<<<B_ * H_ * S_, 256>>>(SC, T_);

    // 15. AT = P . V (cross)
    launch_gemm_f32(SC, V, AT, 0,
                    S_, DH, T_, T_, C_, C_,
                    (long)H_ * S_ * T_, (long)S_ * T_, (long)T_ * C_, DH,
                    (long)S_ * C_, DH,
                    B_ * H_, 1.f, EP_BIAS, false);

    // 16. X2 = X1 + (AT . Wo_c^T + bo_c)
    launch_split(AT, Ahi, Alo, (long)L_ * C_);
    launch_split(Wo_c, Whi, Wlo, (long)C_ * C_);
    launch_tc_gemm(Ahi, Alo, Whi, Wlo, X2, bo_c, X1, 0, 0,
                   L_, C_, C_, C_, EP_RES);

    // 17. LN + MLP modulation
    ln_mod_kernel<<<L_, 256>>>(X2, XM, sst, t, 3, 4);

    // 18. HB = gelu(XM . W_fc1^T + b_fc1)
    launch_split(XM, Ahi, Alo, (long)L_ * C_);
    launch_split(W_fc1, Whi, Wlo, (long)F_ * C_);
    launch_tc_gemm(Ahi, Alo, Whi, Wlo, HB, b_fc1, 0, 0, 0,
                   L_, F_, C_, F_, EP_GELU);

    // 19. out = X2 + gate_mlp * (HB . W_fc2^T + b_fc2)
    launch_split(HB, Ahi, Alo, (long)L_ * F_);
    launch_split(W_fc2, Whi, Wlo, (long)C_ * F_);
    launch_tc_gemm(Ahi, Alo, Whi, Wlo, out, b_fc2, X2, sst + 5 * C_, t + 5 * C_,
                   L_, C_, F_, C_, EP_GATED);
}